// round 2
// baseline (speedup 1.0000x reference)
#include <cuda_runtime.h>
#include <cstdint>
#include <cmath>

#define TQ   4096
#define DM   1024
#define NH   16
#define DH   64

// Scratch (__device__ globals: allocation-free rule)
__device__ float g_qkv[(size_t)TQ * 3 * DM];     // rounded tf32 bits (Q pre-scaled)
__device__ float g_att[(size_t)TQ * DM];         // rounded tf32 bits
__device__ float g_xr[(size_t)TQ * DM];          // x rounded
__device__ float g_wqkvr[(size_t)DM * 3 * DM];   // w_qkv rounded
__device__ float g_wprojr[(size_t)DM * DM];      // w_proj rounded

// ---------------------------------------------------------------------------
// helpers
// ---------------------------------------------------------------------------
__device__ __forceinline__ unsigned f2tf(float x) {
    unsigned u;
    asm("cvt.rna.tf32.f32 %0, %1;" : "=r"(u) : "f"(x));
    return u;
}
__device__ __forceinline__ float f2tff(float x) { return __uint_as_float(f2tf(x)); }

__device__ __forceinline__ void mma_tf32(float* d, const unsigned* a,
                                         unsigned b0, unsigned b1) {
    asm volatile(
        "mma.sync.aligned.m16n8k8.row.col.f32.tf32.tf32.f32 "
        "{%0,%1,%2,%3}, {%4,%5,%6,%7}, {%8,%9}, {%0,%1,%2,%3};\n"
        : "+f"(d[0]), "+f"(d[1]), "+f"(d[2]), "+f"(d[3])
        : "r"(a[0]), "r"(a[1]), "r"(a[2]), "r"(a[3]), "r"(b0), "r"(b1));
}

__device__ __forceinline__ uint32_t s2u(const void* p) {
    uint32_t a;
    asm("{ .reg .u64 t; cvta.to.shared.u64 t, %1; cvt.u32.u64 %0, t; }"
        : "=r"(a) : "l"(p));
    return a;
}
__device__ __forceinline__ void cpa16(uint32_t dst, const void* src) {
    asm volatile("cp.async.cg.shared.global [%0], [%1], 16;\n"
                 :: "r"(dst), "l"(src));
}
__device__ __forceinline__ void cpa_commit() {
    asm volatile("cp.async.commit_group;\n");
}
__device__ __forceinline__ void cpa_wait0() {
    asm volatile("cp.async.wait_group 0;\n");
}

// ---------------------------------------------------------------------------
// tf32 pre-rounding (out of the hot loops)
// ---------------------------------------------------------------------------
__global__ void cvt_tf32_k(const float4* __restrict__ in, float4* __restrict__ out,
                           int n4)
{
    int i = blockIdx.x * blockDim.x + threadIdx.x;
    if (i < n4) {
        float4 v = in[i];
        v.x = f2tff(v.x); v.y = f2tff(v.y); v.z = f2tff(v.z); v.w = f2tff(v.w);
        out[i] = v;
    }
}

// ---------------------------------------------------------------------------
// Tiled tf32 GEMM, cp.async double-buffered.
// BM=128, BN=128, BK=32, 256 threads (warps 4xM x 2xN, warp tile 32x64).
// Inputs are pre-rounded tf32 bits: no cvt in the mainloop.
// qkv_mode: round output; scale cols < DM (the Q block) by 1/8.
// ---------------------------------------------------------------------------
#define AS_STRIDE 36
#define BS_STRIDE 132
#define AS_BUF (128 * AS_STRIDE)   // 4608 floats
#define BS_BUF (32 * BS_STRIDE)    // 4224 floats

__global__ __launch_bounds__(256, 2)
void gemm_tf32(const float* __restrict__ A, const float* __restrict__ B,
               float* __restrict__ C, int M, int N, int K, int qkv_mode)
{
    extern __shared__ float sm[];
    float* As = sm;                       // [2][AS_BUF]
    float* Bs = sm + 2 * AS_BUF;          // [2][BS_BUF]
    const uint32_t sAs = s2u(As);
    const uint32_t sBs = s2u(Bs);

    const int tid  = threadIdx.x;
    const int lane = tid & 31;
    const int warp = tid >> 5;
    const int wm   = warp & 3;
    const int wn   = warp >> 2;
    const int bx   = blockIdx.x;
    const int by   = blockIdx.y;
    const int g    = lane >> 2;
    const int tc   = lane & 3;

    const float* Ablk = A + (size_t)by * 128 * K;
    const float* Bblk = B + (size_t)bx * 128;

    float acc[2][8][4];
#pragma unroll
    for (int mt = 0; mt < 2; mt++)
#pragma unroll
        for (int nt = 0; nt < 8; nt++)
#pragma unroll
            for (int j = 0; j < 4; j++) acc[mt][nt][j] = 0.f;

    auto load_tile = [&](int kt, int buf) {
#pragma unroll
        for (int j = 0; j < 4; j++) {                 // A: 128x32 = 1024 f4
            int idx = tid + j * 256;
            int r   = idx >> 3;
            int c4  = (idx & 7) * 4;
            cpa16(sAs + (uint32_t)(buf * AS_BUF + r * AS_STRIDE + c4) * 4,
                  Ablk + (size_t)r * K + kt + c4);
        }
#pragma unroll
        for (int j = 0; j < 4; j++) {                 // B: 32x128 = 1024 f4
            int idx = tid + j * 256;
            int kr  = idx >> 5;
            int c4  = (idx & 31) * 4;
            cpa16(sBs + (uint32_t)(buf * BS_BUF + kr * BS_STRIDE + c4) * 4,
                  Bblk + (size_t)(kt + kr) * N + c4);
        }
        cpa_commit();
    };

    load_tile(0, 0);
    const int nk = K / 32;

    for (int ki = 0; ki < nk; ki++) {
        cpa_wait0();
        __syncthreads();
        if (ki + 1 < nk) load_tile((ki + 1) * 32, (ki + 1) & 1);

        const float* Ab = As + (ki & 1) * AS_BUF;
        const float* Bb = Bs + (ki & 1) * BS_BUF;

#pragma unroll
        for (int ks = 0; ks < 4; ks++) {
            unsigned a[2][4];
            int col = ks * 8 + tc;
#pragma unroll
            for (int mt = 0; mt < 2; mt++) {
                int row = wm * 32 + mt * 16 + g;
                a[mt][0] = __float_as_uint(Ab[row * AS_STRIDE + col]);
                a[mt][1] = __float_as_uint(Ab[(row + 8) * AS_STRIDE + col]);
                a[mt][2] = __float_as_uint(Ab[row * AS_STRIDE + col + 4]);
                a[mt][3] = __float_as_uint(Ab[(row + 8) * AS_STRIDE + col + 4]);
            }
#pragma unroll
            for (int nt = 0; nt < 8; nt++) {
                int nc = wn * 64 + nt * 8 + g;
                unsigned b0 = __float_as_uint(Bb[col * BS_STRIDE + nc]);
                unsigned b1 = __float_as_uint(Bb[(col + 4) * BS_STRIDE + nc]);
                mma_tf32(acc[0][nt], a[0], b0, b1);
                mma_tf32(acc[1][nt], a[1], b0, b1);
            }
        }
        __syncthreads();
    }

    // epilogue
#pragma unroll
    for (int mt = 0; mt < 2; mt++)
#pragma unroll
        for (int nt = 0; nt < 8; nt++) {
            int r0 = by * 128 + wm * 32 + mt * 16 + g;
            int c0 = bx * 128 + wn * 64 + nt * 8 + 2 * tc;
            float v0 = acc[mt][nt][0], v1 = acc[mt][nt][1];
            float v2 = acc[mt][nt][2], v3 = acc[mt][nt][3];
            if (qkv_mode) {
                float sc = (c0 < DM) ? 0.125f : 1.0f;   // fold q-scale
                v0 = f2tff(v0 * sc); v1 = f2tff(v1 * sc);
                v2 = f2tff(v2 * sc); v3 = f2tff(v3 * sc);
            }
            *(float2*)(C + (size_t)r0 * N + c0)       = make_float2(v0, v1);
            *(float2*)(C + (size_t)(r0 + 8) * N + c0) = make_float2(v2, v3);
        }
}

// ---------------------------------------------------------------------------
// Causal flash attention. BM=128 q-rows per CTA (8 warps x 16 rows),
// KV tiles of 64, double-buffered via cp.async. Inputs are pre-rounded
// (Q pre-scaled). Dynamic smem: Qs | K0 | K1 | V0 | V1 | Ps (rows padded 68).
// ---------------------------------------------------------------------------
#define ROWP 68
#define QS_OFF   0
#define KB_OFF   (128 * ROWP)             // 8704
#define VB_OFF   (KB_OFF + 2 * 64 * ROWP) // 17408
#define PS_OFF   (VB_OFF + 2 * 64 * ROWP) // 26112
#define ATTN_SMEM_FLOATS (PS_OFF + 128 * ROWP)   // 34816

__global__ __launch_bounds__(256, 1) void attn_fwd()
{
    extern __shared__ float sm[];
    float* Qs = sm + QS_OFF;
    float* Ps = sm + PS_OFF;
    const uint32_t sbase = s2u(sm);

    const int tid  = threadIdx.x;
    const int lane = tid & 31;
    const int warp = tid >> 5;
    const int h    = blockIdx.y;
    const int qi   = (int)gridDim.x - 1 - (int)blockIdx.x;  // heavy tiles first
    const int q0   = qi * 128;
    const int g    = lane >> 2;
    const int tc   = lane & 3;

    // ---- prologue: Q tile (128x64) + KV tile 0, one commit group ----
#pragma unroll
    for (int j = 0; j < 8; j++) {               // Q: 2048 f4 / 256 thr
        int idx = tid + j * 256;
        int r   = idx >> 4;
        int c4  = (idx & 15) * 4;
        cpa16(sbase + (uint32_t)(QS_OFF + r * ROWP + c4) * 4,
              g_qkv + (size_t)(q0 + r) * (3 * DM) + h * DH + c4);
    }
#pragma unroll
    for (int j = 0; j < 4; j++) {               // K0 + V0
        int idx = tid + j * 256;
        int r   = idx >> 4;
        int c4  = (idx & 15) * 4;
        const float* base = g_qkv + (size_t)r * (3 * DM) + h * DH + c4;
        cpa16(sbase + (uint32_t)(KB_OFF + r * ROWP + c4) * 4, base + DM);
        cpa16(sbase + (uint32_t)(VB_OFF + r * ROWP + c4) * 4, base + 2 * DM);
    }
    cpa_commit();

    float o[8][4];
#pragma unroll
    for (int nt = 0; nt < 8; nt++)
#pragma unroll
        for (int j = 0; j < 4; j++) o[nt][j] = 0.f;
    float mA = -INFINITY, mB = -INFINITY, lA = 0.f, lB = 0.f;

    const int nt_tiles = 2 * qi + 2;   // kv tiles of 64

    for (int t = 0; t < nt_tiles; t++) {
        cpa_wait0();
        __syncthreads();

        if (t + 1 < nt_tiles) {        // prefetch next KV
            int buf = (t + 1) & 1;
#pragma unroll
            for (int j = 0; j < 4; j++) {
                int idx = tid + j * 256;
                int r   = idx >> 4;
                int c4  = (idx & 15) * 4;
                const float* base =
                    g_qkv + (size_t)((t + 1) * 64 + r) * (3 * DM) + h * DH + c4;
                cpa16(sbase + (uint32_t)(KB_OFF + buf * 64 * ROWP + r * ROWP + c4) * 4,
                      base + DM);
                cpa16(sbase + (uint32_t)(VB_OFF + buf * 64 * ROWP + r * ROWP + c4) * 4,
                      base + 2 * DM);
            }
            cpa_commit();
        }

        const float* Ks = sm + KB_OFF + (t & 1) * 64 * ROWP;
        const float* Vs = sm + VB_OFF + (t & 1) * 64 * ROWP;

        // ---- S = Q @ K^T : warp computes 16 x 64 ----
        float s[8][4];
#pragma unroll
        for (int nt = 0; nt < 8; nt++)
#pragma unroll
            for (int j = 0; j < 4; j++) s[nt][j] = 0.f;

#pragma unroll
        for (int ks = 0; ks < 8; ks++) {
            unsigned a[4];
            int row = warp * 16 + g;
            int col = ks * 8 + tc;
            a[0] = __float_as_uint(Qs[row * ROWP + col]);
            a[1] = __float_as_uint(Qs[(row + 8) * ROWP + col]);
            a[2] = __float_as_uint(Qs[row * ROWP + col + 4]);
            a[3] = __float_as_uint(Qs[(row + 8) * ROWP + col + 4]);
#pragma unroll
            for (int nt = 0; nt < 8; nt++) {
                int nc = nt * 8 + g;
                unsigned b0 = __float_as_uint(Ks[nc * ROWP + col]);
                unsigned b1 = __float_as_uint(Ks[nc * ROWP + col + 4]);
                mma_tf32(s[nt], a, b0, b1);
            }
        }

        // ---- causal mask (only the last two kv tiles can clip) ----
        if (t >= 2 * qi) {
            int qlA = q0 + warp * 16 + g;
            int qlB = qlA + 8;
#pragma unroll
            for (int nt = 0; nt < 8; nt++) {
                int k0 = t * 64 + nt * 8 + 2 * tc;
                if (k0     > qlA) s[nt][0] = -INFINITY;
                if (k0 + 1 > qlA) s[nt][1] = -INFINITY;
                if (k0     > qlB) s[nt][2] = -INFINITY;
                if (k0 + 1 > qlB) s[nt][3] = -INFINITY;
            }
        }

        // ---- online softmax ----
        float rA = -INFINITY, rB = -INFINITY;
#pragma unroll
        for (int nt = 0; nt < 8; nt++) {
            rA = fmaxf(rA, fmaxf(s[nt][0], s[nt][1]));
            rB = fmaxf(rB, fmaxf(s[nt][2], s[nt][3]));
        }
        rA = fmaxf(rA, __shfl_xor_sync(0xffffffffu, rA, 1));
        rA = fmaxf(rA, __shfl_xor_sync(0xffffffffu, rA, 2));
        rB = fmaxf(rB, __shfl_xor_sync(0xffffffffu, rB, 1));
        rB = fmaxf(rB, __shfl_xor_sync(0xffffffffu, rB, 2));

        float mAn = fmaxf(mA, rA), mBn = fmaxf(mB, rB);
        float fA = __expf(mA - mAn), fB = __expf(mB - mBn);

        float sumA = 0.f, sumB = 0.f;
        int rowL = warp * 16 + g;
#pragma unroll
        for (int nt = 0; nt < 8; nt++) {
            float p0 = f2tff(__expf(s[nt][0] - mAn));
            float p1 = f2tff(__expf(s[nt][1] - mAn));
            float p2 = f2tff(__expf(s[nt][2] - mBn));
            float p3 = f2tff(__expf(s[nt][3] - mBn));
            sumA += p0 + p1;
            sumB += p2 + p3;
            int c0 = nt * 8 + 2 * tc;
            Ps[rowL * ROWP + c0]           = p0;
            Ps[rowL * ROWP + c0 + 1]       = p1;
            Ps[(rowL + 8) * ROWP + c0]     = p2;
            Ps[(rowL + 8) * ROWP + c0 + 1] = p3;
        }
        sumA += __shfl_xor_sync(0xffffffffu, sumA, 1);
        sumA += __shfl_xor_sync(0xffffffffu, sumA, 2);
        sumB += __shfl_xor_sync(0xffffffffu, sumB, 1);
        sumB += __shfl_xor_sync(0xffffffffu, sumB, 2);

        lA = lA * fA + sumA;
        lB = lB * fB + sumB;
        mA = mAn; mB = mBn;
#pragma unroll
        for (int nt = 0; nt < 8; nt++) {
            o[nt][0] *= fA; o[nt][1] *= fA;
            o[nt][2] *= fB; o[nt][3] *= fB;
        }
        __syncwarp();   // each warp consumes only its own P rows

        // ---- O += P @ V ----
#pragma unroll
        for (int ks = 0; ks < 8; ks++) {
            unsigned a[4];
            int row = warp * 16 + g;
            int col = ks * 8 + tc;
            a[0] = __float_as_uint(Ps[row * ROWP + col]);
            a[1] = __float_as_uint(Ps[(row + 8) * ROWP + col]);
            a[2] = __float_as_uint(Ps[row * ROWP + col + 4]);
            a[3] = __float_as_uint(Ps[(row + 8) * ROWP + col + 4]);
#pragma unroll
            for (int nt = 0; nt < 8; nt++) {
                unsigned b0 = __float_as_uint(Vs[col * ROWP + nt * 8 + g]);
                unsigned b1 = __float_as_uint(Vs[(col + 4) * ROWP + nt * 8 + g]);
                mma_tf32(o[nt], a, b0, b1);
            }
        }
        __syncwarp();
    }

    // ---- epilogue: normalize, round to tf32 (proj GEMM input), store ----
    float invA = 1.f / lA, invB = 1.f / lB;
    int rowA = q0 + warp * 16 + g;
#pragma unroll
    for (int nt = 0; nt < 8; nt++) {
        int c = h * DH + nt * 8 + 2 * tc;
        *(float2*)(g_att + (size_t)rowA * DM + c) =
            make_float2(f2tff(o[nt][0] * invA), f2tff(o[nt][1] * invA));
        *(float2*)(g_att + (size_t)(rowA + 8) * DM + c) =
            make_float2(f2tff(o[nt][2] * invB), f2tff(o[nt][3] * invB));
    }
}

// ---------------------------------------------------------------------------
// Launch
// ---------------------------------------------------------------------------
extern "C" void kernel_launch(void* const* d_in, const int* in_sizes, int n_in,
                              void* d_out, int out_size)
{
    const float* x      = (const float*)d_in[0];
    const float* w_qkv  = (const float*)d_in[1];
    const float* w_proj = (const float*)d_in[2];
    float* out          = (float*)d_out;

    float *qkv_p, *att_p, *xr_p, *wqkv_p, *wproj_p;
    cudaGetSymbolAddress((void**)&qkv_p,   g_qkv);
    cudaGetSymbolAddress((void**)&att_p,   g_att);
    cudaGetSymbolAddress((void**)&xr_p,    g_xr);
    cudaGetSymbolAddress((void**)&wqkv_p,  g_wqkvr);
    cudaGetSymbolAddress((void**)&wproj_p, g_wprojr);

    const int gemm_smem = (2 * AS_BUF + 2 * BS_BUF) * (int)sizeof(float); // 70656
    const int attn_smem = ATTN_SMEM_FLOATS * (int)sizeof(float);          // 139264
    cudaFuncSetAttribute(gemm_tf32, cudaFuncAttributeMaxDynamicSharedMemorySize,
                         gemm_smem);
    cudaFuncSetAttribute(attn_fwd, cudaFuncAttributeMaxDynamicSharedMemorySize,
                         attn_smem);

    // 0) pre-round inputs to tf32
    cvt_tf32_k<<<(TQ * DM / 4 + 255) / 256, 256>>>((const float4*)x,
                                                   (float4*)xr_p, TQ * DM / 4);
    cvt_tf32_k<<<(DM * 3 * DM / 4 + 255) / 256, 256>>>((const float4*)w_qkv,
                                                       (float4*)wqkv_p,
                                                       DM * 3 * DM / 4);
    cvt_tf32_k<<<(DM * DM / 4 + 255) / 256, 256>>>((const float4*)w_proj,
                                                   (float4*)wproj_p, DM * DM / 4);

    // 1) QKV projection (epilogue rounds + scales Q)
    gemm_tf32<<<dim3(3 * DM / 128, TQ / 128), 256, gemm_smem>>>(
        xr_p, wqkv_p, qkv_p, TQ, 3 * DM, DM, 1);

    // 2) causal attention
    attn_fwd<<<dim3(TQ / 128, NH), 256, attn_smem>>>();

    // 3) output projection (plain fp32 epilogue)
    gemm_tf32<<<dim3(DM / 128, TQ / 128), 256, gemm_smem>>>(
        att_p, wproj_p, out, TQ, DM, DM, 0);
}

// round 4
// speedup vs baseline: 1.5825x; 1.5825x over previous
#include <cuda_runtime.h>
#include <cstdint>
#include <cmath>

#define TQ   4096
#define DM   1024
#define NH   16
#define DH   64

// Scratch (__device__ globals: allocation-free rule)
__device__ float g_qkv[(size_t)TQ * 3 * DM];     // [t][3c] rounded, Q pre-scaled
__device__ float g_att[(size_t)TQ * DM];         // attention out (normal layout)
__device__ float g_xr[(size_t)TQ * DM];          // k-permuted rounded A operand
__device__ float g_wqkvT[(size_t)3 * DM * DM];   // [3DM][DM] transposed+permuted
__device__ float g_wprojT[(size_t)DM * DM];      // [DM][DM]  transposed+permuted

// ---------------------------------------------------------------------------
// helpers
// ---------------------------------------------------------------------------
__device__ __forceinline__ unsigned f2tf(float x) {
    unsigned u;
    asm("cvt.rna.tf32.f32 %0, %1;" : "=r"(u) : "f"(x));
    return u;
}
__device__ __forceinline__ float f2tff(float x) { return __uint_as_float(f2tf(x)); }

__device__ __forceinline__ void mma_tf32(float* d, const unsigned* a,
                                         unsigned b0, unsigned b1) {
    asm volatile(
        "mma.sync.aligned.m16n8k8.row.col.f32.tf32.tf32.f32 "
        "{%0,%1,%2,%3}, {%4,%5,%6,%7}, {%8,%9}, {%0,%1,%2,%3};\n"
        : "+f"(d[0]), "+f"(d[1]), "+f"(d[2]), "+f"(d[3])
        : "r"(a[0]), "r"(a[1]), "r"(a[2]), "r"(a[3]), "r"(b0), "r"(b1));
}

__device__ __forceinline__ uint32_t s2u(const void* p) {
    uint32_t a;
    asm("{ .reg .u64 t; cvta.to.shared.u64 t, %1; cvt.u32.u64 %0, t; }"
        : "=r"(a) : "l"(p));
    return a;
}
__device__ __forceinline__ void cpa16(uint32_t dst, const void* src) {
    asm volatile("cp.async.cg.shared.global [%0], [%1], 16;\n" :: "r"(dst), "l"(src));
}
__device__ __forceinline__ void cpa_commit() {
    asm volatile("cp.async.commit_group;\n");
}
template <int N> __device__ __forceinline__ void cpa_wait() {
    asm volatile("cp.async.wait_group %0;\n" :: "n"(N));
}

// ---------------------------------------------------------------------------
// pre-processing
// k-group permutation: physical p in an 8-group holds logical (p>>1)+((p&1)<<2)
// so a thread's logical (tc, tc+4) pair sits at physical (2tc, 2tc+1) -> LDS.64
// ---------------------------------------------------------------------------
__global__ void cvt_perm_k(const float* __restrict__ in, float* __restrict__ out,
                           int n)   // n = total floats, C divisible by 8
{
    int q = blockIdx.x * blockDim.x + threadIdx.x;   // quad index
    if (q * 4 >= n) return;
    int gp    = q * 4;
    int group = gp & ~7;
    int off   = gp & 7;                              // 0 or 4
    float4 v;
    if (off == 0)
        v = make_float4(in[group + 0], in[group + 4], in[group + 1], in[group + 5]);
    else
        v = make_float4(in[group + 2], in[group + 6], in[group + 3], in[group + 7]);
    v.x = f2tff(v.x); v.y = f2tff(v.y); v.z = f2tff(v.z); v.w = f2tff(v.w);
    *(float4*)(out + gp) = v;
}

// in [R][C] -> out [C][R] with inner (k=R) dim permuted in 8-groups, rounded.
__global__ void wtrans_perm(const float* __restrict__ in,
                            float* __restrict__ out, int R, int C)
{
    __shared__ float t[32][33];
    int c0 = blockIdx.x * 32, r0 = blockIdx.y * 32;
    int tx = threadIdx.x, ty = threadIdx.y;
#pragma unroll
    for (int i = 0; i < 4; i++)
        t[ty + 8 * i][tx] = in[(size_t)(r0 + ty + 8 * i) * C + c0 + tx];
    __syncthreads();
    int p   = tx & 7;
    int txl = (tx & ~7) | ((p >> 1) + ((p & 1) << 2));
#pragma unroll
    for (int i = 0; i < 4; i++)
        out[(size_t)(c0 + ty + 8 * i) * R + r0 + tx] = f2tff(t[txl][ty + 8 * i]);
}

// ---------------------------------------------------------------------------
// tf32 GEMM on k-permuted operands: C[M,N] = A[M,K] @ B[N,K]^T
// BM=128, BN=128, BK=32, 256 thr (warps 4xM x 2xN, warp tile 32x64),
// 2-stage cp.async double buffer, all fragment loads LDS.64.
// MODE 1: round output; scale cols < DM by 0.125 (Q block).
// ---------------------------------------------------------------------------
#define GST 40                      // smem row stride (floats)
#define GSTAGE (2 * 128 * GST)      // floats per stage (A then B)

template <int MODE>
__global__ __launch_bounds__(256, 2)
void gemm_tf32p(const float* __restrict__ A, const float* __restrict__ B,
                float* __restrict__ C, int M, int N, int K)
{
    __shared__ float sm[2 * GSTAGE];
    const uint32_t s0 = s2u(sm);

    const int tid  = threadIdx.x;
    const int lane = tid & 31;
    const int warp = tid >> 5;
    const int wm   = warp & 3;
    const int wn   = warp >> 2;
    const int bx   = blockIdx.x;
    const int by   = blockIdx.y;
    const int g    = lane >> 2;
    const int tc   = lane & 3;

    const float* Ab = A + (size_t)(by * 128) * K;
    const float* Bb = B + (size_t)(bx * 128) * K;

    float acc[2][8][4];
#pragma unroll
    for (int mt = 0; mt < 2; mt++)
#pragma unroll
        for (int nt = 0; nt < 8; nt++)
#pragma unroll
            for (int j = 0; j < 4; j++) acc[mt][nt][j] = 0.f;

    auto load_stage = [&](int s, int buf) {
        uint32_t dA = s0 + (uint32_t)(buf * GSTAGE) * 4;
        uint32_t dB = dA + (uint32_t)(128 * GST) * 4;
#pragma unroll
        for (int j = 0; j < 4; j++) {
            int idx = tid + j * 256;
            int r = idx >> 3, c4 = (idx & 7) * 4;
            cpa16(dA + (uint32_t)(r * GST + c4) * 4, Ab + (size_t)r * K + s * 32 + c4);
            cpa16(dB + (uint32_t)(r * GST + c4) * 4, Bb + (size_t)r * K + s * 32 + c4);
        }
        cpa_commit();
    };

    load_stage(0, 0);
    load_stage(1, 1);

    const int S = K / 32;
    for (int s = 0; s < S; s++) {
        if (s + 1 < S) cpa_wait<1>(); else cpa_wait<0>();
        __syncthreads();

        const float* As = sm + (s & 1) * GSTAGE;
        const float* Bs = As + 128 * GST;

#pragma unroll
        for (int ks = 0; ks < 4; ks++) {
            int kc = ks * 8 + 2 * tc;      // physical pair = logical (tc, tc+4)
            unsigned a[2][4];
#pragma unroll
            for (int mt = 0; mt < 2; mt++) {
                int row = wm * 32 + mt * 16 + g;
                float2 lo = *(const float2*)(As + row * GST + kc);
                float2 hi = *(const float2*)(As + (row + 8) * GST + kc);
                a[mt][0] = __float_as_uint(lo.x);
                a[mt][1] = __float_as_uint(hi.x);
                a[mt][2] = __float_as_uint(lo.y);
                a[mt][3] = __float_as_uint(hi.y);
            }
#pragma unroll
            for (int nt = 0; nt < 8; nt++) {
                int nr = wn * 64 + nt * 8 + g;
                float2 b = *(const float2*)(Bs + nr * GST + kc);
                mma_tf32(acc[0][nt], a[0], __float_as_uint(b.x), __float_as_uint(b.y));
                mma_tf32(acc[1][nt], a[1], __float_as_uint(b.x), __float_as_uint(b.y));
            }
        }
        __syncthreads();
        if (s + 2 < S) load_stage(s + 2, s & 1);
    }

    // epilogue
#pragma unroll
    for (int mt = 0; mt < 2; mt++)
#pragma unroll
        for (int nt = 0; nt < 8; nt++) {
            int r0 = by * 128 + wm * 32 + mt * 16 + g;
            int c0 = bx * 128 + wn * 64 + nt * 8 + 2 * tc;
            float v0 = acc[mt][nt][0], v1 = acc[mt][nt][1];
            float v2 = acc[mt][nt][2], v3 = acc[mt][nt][3];
            if (MODE == 1) {
                float sc = (c0 < DM) ? 0.125f : 1.0f;
                v0 = f2tff(v0 * sc); v1 = f2tff(v1 * sc);
                v2 = f2tff(v2 * sc); v3 = f2tff(v3 * sc);
            }
            *(float2*)(C + (size_t)r0 * N + c0)       = make_float2(v0, v1);
            *(float2*)(C + (size_t)(r0 + 8) * N + c0) = make_float2(v2, v3);
        }
}

// ---------------------------------------------------------------------------
// Causal flash attention (round-1 proven shape: 64 q-rows, 4 warps, 3 CTA/SM).
// Inputs pre-rounded tf32, Q pre-scaled. K/V/Q via cp.async.
// ---------------------------------------------------------------------------
#define ROWP 68
__global__ __launch_bounds__(128) void attn_fwd()
{
    extern __shared__ float sm[];
    float* Qs = sm;
    float* Ks = Qs + 64 * ROWP;
    float* Vs = Ks + 64 * ROWP;
    float* Ps = Vs + 64 * ROWP;
    const uint32_t sb = s2u(sm);

    const int tid  = threadIdx.x;
    const int lane = tid & 31;
    const int warp = tid >> 5;
    const int h    = blockIdx.y;
    const int qt   = (int)gridDim.x - 1 - (int)blockIdx.x;  // heavy tiles first
    const int q0   = qt * 64;
    const int g    = lane >> 2;
    const int tc   = lane & 3;

    // ---- prologue: Q tile via cp.async ----
#pragma unroll
    for (int i = 0; i < 8; i++) {
        int idx = tid + i * 128;
        int r   = idx >> 4;
        int c4  = (idx & 15) * 4;
        cpa16(sb + (uint32_t)(r * ROWP + c4) * 4,
              g_qkv + (size_t)(q0 + r) * (3 * DM) + h * DH + c4);
    }
    cpa_commit();

    float o[8][4];
#pragma unroll
    for (int nt = 0; nt < 8; nt++)
#pragma unroll
        for (int j = 0; j < 4; j++) o[nt][j] = 0.f;
    float mA = -INFINITY, mB = -INFINITY, lA = 0.f, lB = 0.f;

    for (int t = 0; t <= qt; t++) {
        __syncthreads();                  // prior tile compute done
#pragma unroll
        for (int i = 0; i < 8; i++) {
            int idx = tid + i * 128;
            int r   = idx >> 4;
            int c4  = (idx & 15) * 4;
            const float* base = g_qkv + (size_t)(t * 64 + r) * (3 * DM) + h * DH + c4;
            cpa16(sb + (uint32_t)((64 * ROWP) + r * ROWP + c4) * 4, base + DM);
            cpa16(sb + (uint32_t)((128 * ROWP) + r * ROWP + c4) * 4, base + 2 * DM);
        }
        cpa_commit();
        cpa_wait<0>();
        __syncthreads();

        // ---- S = Q @ K^T : warp computes 16 x 64 ----
        float s[8][4];
#pragma unroll
        for (int nt = 0; nt < 8; nt++)
#pragma unroll
            for (int j = 0; j < 4; j++) s[nt][j] = 0.f;

#pragma unroll
        for (int ks = 0; ks < 8; ks++) {
            unsigned a[4];
            int row = warp * 16 + g;
            int col = ks * 8 + tc;
            a[0] = __float_as_uint(Qs[row * ROWP + col]);
            a[1] = __float_as_uint(Qs[(row + 8) * ROWP + col]);
            a[2] = __float_as_uint(Qs[row * ROWP + col + 4]);
            a[3] = __float_as_uint(Qs[(row + 8) * ROWP + col + 4]);
#pragma unroll
            for (int nt = 0; nt < 8; nt++) {
                int nc = nt * 8 + g;
                unsigned b0 = __float_as_uint(Ks[nc * ROWP + col]);
                unsigned b1 = __float_as_uint(Ks[nc * ROWP + col + 4]);
                mma_tf32(s[nt], a, b0, b1);
            }
        }

        // ---- causal mask on diagonal tile ----
        if (t == qt) {
            int qlA = warp * 16 + g;
            int qlB = qlA + 8;
#pragma unroll
            for (int nt = 0; nt < 8; nt++) {
                int k0 = nt * 8 + 2 * tc;
                if (k0     > qlA) s[nt][0] = -INFINITY;
                if (k0 + 1 > qlA) s[nt][1] = -INFINITY;
                if (k0     > qlB) s[nt][2] = -INFINITY;
                if (k0 + 1 > qlB) s[nt][3] = -INFINITY;
            }
        }

        // ---- online softmax ----
        float rA = -INFINITY, rB = -INFINITY;
#pragma unroll
        for (int nt = 0; nt < 8; nt++) {
            rA = fmaxf(rA, fmaxf(s[nt][0], s[nt][1]));
            rB = fmaxf(rB, fmaxf(s[nt][2], s[nt][3]));
        }
        rA = fmaxf(rA, __shfl_xor_sync(0xffffffffu, rA, 1));
        rA = fmaxf(rA, __shfl_xor_sync(0xffffffffu, rA, 2));
        rB = fmaxf(rB, __shfl_xor_sync(0xffffffffu, rB, 1));
        rB = fmaxf(rB, __shfl_xor_sync(0xffffffffu, rB, 2));

        float mAn = fmaxf(mA, rA), mBn = fmaxf(mB, rB);
        float fA = __expf(mA - mAn), fB = __expf(mB - mBn);

        float sumA = 0.f, sumB = 0.f;
        int rowL = warp * 16 + g;
#pragma unroll
        for (int nt = 0; nt < 8; nt++) {
            float p0 = f2tff(__expf(s[nt][0] - mAn));
            float p1 = f2tff(__expf(s[nt][1] - mAn));
            float p2 = f2tff(__expf(s[nt][2] - mBn));
            float p3 = f2tff(__expf(s[nt][3] - mBn));
            sumA += p0 + p1;
            sumB += p2 + p3;
            int c0 = nt * 8 + 2 * tc;
            Ps[rowL * ROWP + c0]           = p0;
            Ps[rowL * ROWP + c0 + 1]       = p1;
            Ps[(rowL + 8) * ROWP + c0]     = p2;
            Ps[(rowL + 8) * ROWP + c0 + 1] = p3;
        }
        sumA += __shfl_xor_sync(0xffffffffu, sumA, 1);
        sumA += __shfl_xor_sync(0xffffffffu, sumA, 2);
        sumB += __shfl_xor_sync(0xffffffffu, sumB, 1);
        sumB += __shfl_xor_sync(0xffffffffu, sumB, 2);

        lA = lA * fA + sumA;
        lB = lB * fB + sumB;
        mA = mAn; mB = mBn;
#pragma unroll
        for (int nt = 0; nt < 8; nt++) {
            o[nt][0] *= fA; o[nt][1] *= fA;
            o[nt][2] *= fB; o[nt][3] *= fB;
        }
        __syncwarp();   // each warp consumes only its own P rows

        // ---- O += P @ V ----
#pragma unroll
        for (int ks = 0; ks < 8; ks++) {
            unsigned a[4];
            int row = warp * 16 + g;
            int col = ks * 8 + tc;
            a[0] = __float_as_uint(Ps[row * ROWP + col]);
            a[1] = __float_as_uint(Ps[(row + 8) * ROWP + col]);
            a[2] = __float_as_uint(Ps[row * ROWP + col + 4]);
            a[3] = __float_as_uint(Ps[(row + 8) * ROWP + col + 4]);
#pragma unroll
            for (int nt = 0; nt < 8; nt++) {
                unsigned b0 = __float_as_uint(Vs[col * ROWP + nt * 8 + g]);
                unsigned b1 = __float_as_uint(Vs[(col + 4) * ROWP + nt * 8 + g]);
                mma_tf32(o[nt], a, b0, b1);
            }
        }
    }

    // ---- epilogue: normalize, round (proj GEMM input), store normal layout ----
    float invA = 1.f / lA, invB = 1.f / lB;
    int rowA = q0 + warp * 16 + g;
#pragma unroll
    for (int nt = 0; nt < 8; nt++) {
        int c = h * DH + nt * 8 + 2 * tc;
        *(float2*)(g_att + (size_t)rowA * DM + c) =
            make_float2(f2tff(o[nt][0] * invA), f2tff(o[nt][1] * invA));
        *(float2*)(g_att + (size_t)(rowA + 8) * DM + c) =
            make_float2(f2tff(o[nt][2] * invB), f2tff(o[nt][3] * invB));
    }
}

// ---------------------------------------------------------------------------
// Launch
// ---------------------------------------------------------------------------
extern "C" void kernel_launch(void* const* d_in, const int* in_sizes, int n_in,
                              void* d_out, int out_size)
{
    const float* x      = (const float*)d_in[0];
    const float* w_qkv  = (const float*)d_in[1];
    const float* w_proj = (const float*)d_in[2];
    float* out          = (float*)d_out;

    float *qkv_p, *att_p, *xr_p, *wqkvT_p, *wprojT_p;
    cudaGetSymbolAddress((void**)&qkv_p,    g_qkv);
    cudaGetSymbolAddress((void**)&att_p,    g_att);
    cudaGetSymbolAddress((void**)&xr_p,     g_xr);
    cudaGetSymbolAddress((void**)&wqkvT_p,  g_wqkvT);
    cudaGetSymbolAddress((void**)&wprojT_p, g_wprojT);

    const int attn_smem = 4 * 64 * ROWP * (int)sizeof(float);   // 69632 -> 3 CTA/SM
    cudaFuncSetAttribute(attn_fwd, cudaFuncAttributeMaxDynamicSharedMemorySize,
                         attn_smem);

    // 0) pre-process: round + k-permute A operands; transpose+round+permute weights
    cvt_perm_k<<<(TQ * DM / 4 + 255) / 256, 256>>>(x, xr_p, TQ * DM);
    wtrans_perm<<<dim3(3 * DM / 32, DM / 32), dim3(32, 8)>>>(w_qkv, wqkvT_p,
                                                             DM, 3 * DM);
    wtrans_perm<<<dim3(DM / 32, DM / 32), dim3(32, 8)>>>(w_proj, wprojT_p,
                                                         DM, DM);

    // 1) QKV projection: [4096,1024] @ [3072,1024]^T (rounds + scales Q)
    gemm_tf32p<1><<<dim3(3 * DM / 128, TQ / 128), 256>>>(
        xr_p, wqkvT_p, qkv_p, TQ, 3 * DM, DM);

    // 2) causal attention
    attn_fwd<<<dim3(TQ / 64, NH), 128, attn_smem>>>();

    // 3) permute attention output for the proj GEMM (reuse g_xr)
    cvt_perm_k<<<(TQ * DM / 4 + 255) / 256, 256>>>(att_p, xr_p, TQ * DM);

    // 4) output projection
    gemm_tf32p<0><<<dim3(DM / 128, TQ / 128), 256>>>(
        xr_p, wprojT_p, out, TQ, DM, DM);
}